// round 15
// baseline (speedup 1.0000x reference)
#include <cuda_runtime.h>
#include <cstdint>

// Problem constants
constexpr int B_   = 8;
constexpr int H_   = 8;
constexpr int LQ_  = 1024;
constexpr int LM_  = 4096;
constexpr int DM_  = 512;
constexpr int DK_  = 64;
constexpr int TOPK_ = 32;

// Attention kernel tiling
constexpr int QT   = 32;    // queries per block (4 rows per warp)
constexpr int CK   = 128;   // key chunk cached in smem (as 64 key-pairs)

// Scratch (static device arrays: allocation-free)
__device__ float g_q[B_*H_*LQ_*DK_];   // 16 MB  [B,H,LQ,Dk]
__device__ float g_k[B_*H_*LM_*DK_];   // 64 MB  [B,H,LM,Dk]
__device__ float g_v[B_*H_*LM_*DK_];   // 64 MB  [B,H,LM,Dk]
__device__ float g_x[B_*LQ_*DM_];      // 16 MB  [B,LQ,DM] pre-output-proj

// ---------------- attention smem layout (float units) ----------------------
// qd: 32 rows x 64 dims, duplicated (q,q) ull   -> 16 KB
// kp: 64 key-pairs x 64 dims, packed (kA,kB) ull, xor-swizzled -> 32 KB
constexpr int OFF_QD  = 0;                  // 4096 floats (2048 ull)
constexpr int OFF_KP  = OFF_QD + 4096;      // 8192 floats (4096 ull)
constexpr int SMEM_FLOATS = OFF_KP + 8192;
constexpr int SMEM_BYTES  = SMEM_FLOATS * 4;   // 49152 B -> 3 blocks/SM

// order-preserving float -> uint, and inverse
__device__ __forceinline__ unsigned ordu(float x) {
    unsigned u = __float_as_uint(x);
    return (u & 0x80000000u) ? ~u : (u | 0x80000000u);
}
__device__ __forceinline__ float iordu(unsigned v) {
    unsigned u = (v & 0x80000000u) ? (v ^ 0x80000000u) : ~v;
    return __uint_as_float(u);
}

// ---------------- packed f32x2 primitives (lanewise IEEE fp32) -------------
typedef unsigned long long ull;

__device__ __forceinline__ ull pack2(float lo, float hi) {
    ull d; asm("mov.b64 %0, {%1, %2};" : "=l"(d) : "f"(lo), "f"(hi)); return d;
}
__device__ __forceinline__ void unpack2(ull v, float& lo, float& hi) {
    asm("mov.b64 {%0, %1}, %2;" : "=f"(lo), "=f"(hi) : "l"(v));
}
__device__ __forceinline__ ull fma2(ull a, ull b, ull c) {
    ull d; asm("fma.rn.f32x2 %0, %1, %2, %3;" : "=l"(d) : "l"(a), "l"(b), "l"(c)); return d;
}
__device__ __forceinline__ ull mul2(ull a, ull b) {
    ull d; asm("mul.rn.f32x2 %0, %1, %2;" : "=l"(d) : "l"(a), "l"(b)); return d;
}
__device__ __forceinline__ ull add2(ull a, ull b) {
    ull d; asm("add.rn.f32x2 %0, %1, %2;" : "=l"(d) : "l"(a), "l"(b)); return d;
}

// B smem row layout: per-tx pad to 10 floats -> 16 distinct banks for the
// 16 tx groups (10*tx mod 32 all distinct), 8B-aligned pairs for LDS.64.
constexpr int BROW = 160;   // 16 tx-groups * 10 floats
__device__ __forceinline__ int bswz(int n) { return (n >> 3) * 10 + (n & 7); }

// ---------------------------------------------------------------------------
// Shared SGEMM body (VERBATIM round-8 best): C = A[M,512] @ W[512,512]^T + bias.
// f32x2 packed FMA inner loop; per-element arithmetic (values and order)
// IDENTICAL to the scalar two-level version of rounds 2-7.
// 256 threads, 8x8 per thread, 128x128 tile at (m0, n0).
// ---------------------------------------------------------------------------
__device__ __forceinline__ void gemm_body(
    const float* __restrict__ A, const float* __restrict__ W,
    const float* __restrict__ bias, float* __restrict__ C,
    int L, int head_major, int m0, int n0)
{
    __shared__ __align__(16) float AsD[2][8][256];   // duplicated A: 16 KB
    __shared__ __align__(16) float Bs [2][8][BROW];  // padded B: 10 KB

    const int t  = threadIdx.x;
    const int tx = t & 15;
    const int ty = t >> 4;
    const int lr = t >> 1;
    const int lc = (t & 1) << 2;

    const float* Ap = A + (size_t)(m0 + lr) * DM_ + lc;
    const float* Wp = W + (size_t)(n0 + lr) * DM_ + lc;
    const int bofs = bswz(lr);

    // prologue: stage k-tile 0 into buffer 0
    {
        float4 av = *(const float4*)(Ap);
        float4 wv = *(const float4*)(Wp);
        ((ull*)AsD[0][lc+0])[lr] = pack2(av.x, av.x);
        ((ull*)AsD[0][lc+1])[lr] = pack2(av.y, av.y);
        ((ull*)AsD[0][lc+2])[lr] = pack2(av.z, av.z);
        ((ull*)AsD[0][lc+3])[lr] = pack2(av.w, av.w);
        Bs[0][lc+0][bofs] = wv.x;
        Bs[0][lc+1][bofs] = wv.y;
        Bs[0][lc+2][bofs] = wv.z;
        Bs[0][lc+3][bofs] = wv.w;
    }
    __syncthreads();

    ull acc2[8][4];
    #pragma unroll
    for (int i = 0; i < 8; i++)
        #pragma unroll
        for (int j = 0; j < 4; j++) acc2[i][j] = pack2(0.f, 0.f);

    #pragma unroll 1
    for (int k0 = 0; k0 < DM_; k0 += 8) {
        const int  p    = (k0 >> 3) & 1;
        const bool more = (k0 + 8) < DM_;
        float4 av, wv;
        if (more) {
            av = *(const float4*)(Ap + k0 + 8);
            wv = *(const float4*)(Wp + k0 + 8);
        }

        ull cacc2[8][4];
        #pragma unroll
        for (int k = 0; k < 8; k++) {
            // a (duplicated) : 8 ull = 4x LDS.128 broadcast
            ull a2[8];
            {
                const ulonglong2* ar = (const ulonglong2*)&AsD[p][k][0];
                #pragma unroll
                for (int ii = 0; ii < 4; ii++) {
                    ulonglong2 v = ar[ty*4 + ii];
                    a2[2*ii]   = v.x;
                    a2[2*ii+1] = v.y;
                }
            }
            // b pairs: 4x LDS.64, conflict-free via 10-float padding
            ull b2[4];
            {
                const ull* br = (const ull*)&Bs[p][k][tx*10];
                #pragma unroll
                for (int j = 0; j < 4; j++) b2[j] = br[j];
            }
            if (k == 0) {
                #pragma unroll
                for (int i = 0; i < 8; i++)
                    #pragma unroll
                    for (int j = 0; j < 4; j++)
                        cacc2[i][j] = mul2(a2[i], b2[j]);
            } else {
                #pragma unroll
                for (int i = 0; i < 8; i++)
                    #pragma unroll
                    for (int j = 0; j < 4; j++)
                        cacc2[i][j] = fma2(a2[i], b2[j], cacc2[i][j]);
            }
        }
        #pragma unroll
        for (int i = 0; i < 8; i++)
            #pragma unroll
            for (int j = 0; j < 4; j++)
                acc2[i][j] = add2(acc2[i][j], cacc2[i][j]);

        if (more) {
            const int q = p ^ 1;
            ((ull*)AsD[q][lc+0])[lr] = pack2(av.x, av.x);
            ((ull*)AsD[q][lc+1])[lr] = pack2(av.y, av.y);
            ((ull*)AsD[q][lc+2])[lr] = pack2(av.z, av.z);
            ((ull*)AsD[q][lc+3])[lr] = pack2(av.w, av.w);
            Bs[q][lc+0][bofs] = wv.x;
            Bs[q][lc+1][bofs] = wv.y;
            Bs[q][lc+2][bofs] = wv.z;
            Bs[q][lc+3][bofs] = wv.w;
        }
        __syncthreads();
    }

    #pragma unroll
    for (int i = 0; i < 8; i++) {
        int m  = m0 + ty*8 + i;
        int bb_ = m / L;
        int l   = m - bb_ * L;
        #pragma unroll
        for (int j = 0; j < 4; j++) {
            float lo, hi;
            unpack2(acc2[i][j], lo, hi);
            int n0j = n0 + tx*8 + 2*j;
            float v0 = lo + bias[n0j];
            float v1 = hi + bias[n0j + 1];
            if (head_major) {
                int hh0 = n0j >> 6, dk0 = n0j & 63;
                int hh1 = (n0j+1) >> 6, dk1 = (n0j+1) & 63;
                C[((size_t)(bb_*H_ + hh0) * L + l) * DK_ + dk0] = v0;
                C[((size_t)(bb_*H_ + hh1) * L + l) * DK_ + dk1] = v1;
            } else {
                C[(size_t)m * DM_ + n0j]     = v0;
                C[(size_t)m * DM_ + n0j + 1] = v1;
            }
        }
    }
}

// Merged Q/K/V projection: grid (64 + 256 + 256, 4).
__global__ void __launch_bounds__(256, 1)
qkv_gemm_kernel(const float* __restrict__ q_in, const float* __restrict__ k_in,
                const float* __restrict__ v_in,
                const float* __restrict__ Wq, const float* __restrict__ bq,
                const float* __restrict__ Wk, const float* __restrict__ bk,
                const float* __restrict__ Wv, const float* __restrict__ bv,
                float* __restrict__ pq, float* __restrict__ pk, float* __restrict__ pv)
{
    const int bx = blockIdx.x;
    const float *A, *W, *bias; float* C; int L, mblk;
    if (bx < 64)        { A = q_in; W = Wq; bias = bq; C = pq; L = LQ_; mblk = bx; }
    else if (bx < 320)  { A = k_in; W = Wk; bias = bk; C = pk; L = LM_; mblk = bx - 64; }
    else                { A = v_in; W = Wv; bias = bv; C = pv; L = LM_; mblk = bx - 320; }
    gemm_body(A, W, bias, C, L, 1, mblk * 128, blockIdx.y * 128);
}

// Output projection: plain row-major.
__global__ void __launch_bounds__(256, 1)
out_gemm_kernel(const float* __restrict__ A, const float* __restrict__ W,
                const float* __restrict__ bias, float* __restrict__ C)
{
    gemm_body(A, W, bias, C, LQ_, 0, blockIdx.x * 128, blockIdx.y * 128);
}

// ---------------------------------------------------------------------------
// Fused scores + EXACT top-32 + softmax + V gather — KEY-PAIR f32x2 version:
//   K staged as packed pairs kp[p][d] = (K[rA], K[rB]) (packing amortized in
//   staging, NOT in the inner loop); Q stored duplicated (q,q) in smem.
//   Inner loop: 12 LDS.128 + 40 f32x2 ops per d4, ZERO register packs
//   (round 14 spent ~32 MOV slots/d4 duplicating K in registers).
// Per-lane-half contraction is the round-14 statement verbatim
// (t=mul2; 3x fma2; acc=add2, d4 ascending) with identical operand values
// => scores bit-identical to round 14 (rel_err 8.774736e-4).
// Lane's keys {lane, 32+lane, 64+lane, 96+lane}, visited sub-ascending —
// selection algorithm and order verbatim rounds 13/14.
// ---------------------------------------------------------------------------
__global__ void __launch_bounds__(256, 3)
attn_topk_kernel(const float* __restrict__ gq, const float* __restrict__ gk,
                 const float* __restrict__ gv, float* __restrict__ gx)
{
    extern __shared__ float sm[];
    ull* qd = (ull*)(sm + OFF_QD);   // 32 rows x 64 dims, (q,q) dup
    ull* kp = (ull*)(sm + OFF_KP);   // 64 pairs x 64 dims, (kA,kB), swizzled

    const int t    = threadIdx.x;
    const int lane = t & 31;
    const int w    = t >> 5;               // warp id; owns rows 4w..4w+3
    const int qt0  = blockIdx.x * QT;
    const int h    = blockIdx.y;
    const int b    = blockIdx.z;
    const unsigned FULL = 0xffffffffu;

    // ---- stage Q duplicated (once per block): qd[r*64+d] = (q,q) ----
    const float* qbase = gq + ((size_t)(b*H_ + h) * LQ_ + qt0) * DK_;
    #pragma unroll
    for (int i = t; i < QT*DK_; i += 256) {
        float q = qbase[i];
        qd[i] = pack2(q, q);
    }

    const float* kbase = gk + (size_t)(b*H_ + h) * LM_ * DK_;

    // running top-32 state for the four rows owned by this warp
    unsigned bval[4] = {0u, 0u, 0u, 0u};
    int      bidx[4] = {0, 0, 0, 0};
    unsigned m[4]    = {0u, 0u, 0u, 0u};

    // lane's two pair rows: pA -> keys (lane, 32+lane), pB -> (64+lane, 96+lane)
    const int pA = lane;
    const int pB = 32 + lane;
    const int sA = pA & 15;
    const int sB = pB & 15;

    #pragma unroll 1
    for (int c0 = 0; c0 < LM_; c0 += CK) {
        __syncthreads();  // all warps done reading kp of previous chunk
                          // (also covers qd prep on first iteration)

        // ---- stage K chunk as packed key-pairs, xor-swizzled (16B units):
        //      pair p < 32 -> rows (p, p+32); p >= 32 -> rows (p+32, p+64) ----
        #pragma unroll
        for (int i = t; i < 64*16; i += 256) {
            int p  = i >> 4, d4 = i & 15;
            int rA = (p < 32) ? p : p + 32;
            int rB = rA + 32;
            float4 a = ((const float4*)(kbase + (size_t)(c0 + rA) * DK_))[d4];
            float4 bv4 = ((const float4*)(kbase + (size_t)(c0 + rB) * DK_))[d4];
            int s = p & 15;
            ulonglong2* kp2 = (ulonglong2*)kp;
            ulonglong2 v0; v0.x = pack2(a.x, bv4.x); v0.y = pack2(a.y, bv4.y);
            ulonglong2 v1; v1.x = pack2(a.z, bv4.z); v1.y = pack2(a.w, bv4.w);
            kp2[(p << 5) | ((d4*2)     ^ s)] = v0;
            kp2[(p << 5) | ((d4*2 + 1) ^ s)] = v1;
        }
        __syncthreads();

        // ---- scores in f32x2 registers: 2 key-pairs x 4 rows ----
        ull accA[4], accB[4];   // [row]; lo=keyA, hi=keyB
        #pragma unroll
        for (int r = 0; r < 4; r++) { accA[r] = pack2(0.f, 0.f); accB[r] = pack2(0.f, 0.f); }

        {
            const ulonglong2* kp2 = (const ulonglong2*)kp;
            const ulonglong2* qd2 = (const ulonglong2*)(qd + (4*w) * DK_);
            #pragma unroll 4
            for (int d4 = 0; d4 < DK_/4; d4++) {
                const int g = d4*2;
                ulonglong2 ka0 = kp2[(pA << 5) | ( g      ^ sA)];  // dims d,d+1
                ulonglong2 ka1 = kp2[(pA << 5) | ((g + 1) ^ sA)];  // dims d+2,d+3
                ulonglong2 kb0 = kp2[(pB << 5) | ( g      ^ sB)];
                ulonglong2 kb1 = kp2[(pB << 5) | ((g + 1) ^ sB)];
                #pragma unroll
                for (int r = 0; r < 4; r++) {
                    ulonglong2 q01 = qd2[r*32 + g];       // dims d,d+1 (dup)
                    ulonglong2 q23 = qd2[r*32 + g + 1];   // dims d+2,d+3 (dup)
                    ull tA = mul2(ka0.x, q01.x);
                    tA = fma2(ka0.y, q01.y, tA);
                    tA = fma2(ka1.x, q23.x, tA);
                    tA = fma2(ka1.y, q23.y, tA);
                    accA[r] = add2(accA[r], tA);

                    ull tB = mul2(kb0.x, q01.x);
                    tB = fma2(kb0.y, q01.y, tB);
                    tB = fma2(kb1.x, q23.x, tB);
                    tB = fma2(kb1.y, q23.y, tB);
                    accB[r] = add2(accB[r], tB);
                }
            }
        }

        // unpack to per-row ordered uints: uu[sub][r]
        unsigned uu[4][4];
        #pragma unroll
        for (int r = 0; r < 4; r++) {
            float a0, a1, b0, b1;
            unpack2(accA[r], a0, a1);
            unpack2(accB[r], b0, b1);
            uu[0][r] = ordu(a0 * 0.125f);   // key lane       (1/sqrt(64))
            uu[1][r] = ordu(a1 * 0.125f);   // key 32+lane
            uu[2][r] = ordu(b0 * 0.125f);   // key 64+lane
            uu[3][r] = ordu(b1 * 0.125f);   // key 96+lane
        }

        // ---- select on register scores; batch order: sub ascending ----
        #pragma unroll 1
        for (int r = 0; r < 4; r++) {
            unsigned u0 = uu[0][r], u1 = uu[1][r], u2 = uu[2][r], u3 = uu[3][r];

            if (c0 != 0) {
                // fast path: skip row if nothing exceeds m[r] (exact: m is
                // monotone non-decreasing, so skipping is equivalent).
                bool any = (u0 > m[r]) | (u1 > m[r]) | (u2 > m[r]) | (u3 > m[r]);
                if (__ballot_sync(FULL, any) == 0u) continue;
            }

            #pragma unroll 1
            for (int sub = 0; sub < 4; sub++) {
                unsigned u = (sub == 0) ? u0 : (sub == 1) ? u1 : (sub == 2) ? u2 : u3;
                const int i0 = c0 + sub*32;

                if (c0 == 0 && sub == 0) {          // initial fill
                    bval[r] = u; bidx[r] = lane;
                    m[r] = __reduce_min_sync(FULL, bval[r]);
                    continue;
                }

                unsigned hit = __ballot_sync(FULL, u > m[r]);
                while (hit) {                        // warp-uniform rare path
                    int s = __ffs(hit) - 1; hit &= hit - 1;
                    unsigned uc = __shfl_sync(FULL, u, s);
                    if (uc > m[r]) {                 // recheck vs updated m
                        int ic = i0 + s;
                        unsigned em = __ballot_sync(FULL, bval[r] == m[r]);
                        int el;
                        if (__popc(em) > 1) {
                            // tie on min: evict LARGER index (jax keeps lower)
                            int cb = ((em >> lane) & 1) ? bidx[r] : -1;
                            int mx = __reduce_max_sync(FULL, cb);
                            el = __ffs(__ballot_sync(FULL,
                                    (bval[r] == m[r]) && (bidx[r] == mx))) - 1;
                        } else {
                            el = __ffs(em) - 1;
                        }
                        if (lane == el) { bval[r] = uc; bidx[r] = ic; }
                        m[r] = __reduce_min_sync(FULL, bval[r]);
                    }
                }
            }
        }
    }

    // ---- softmax + weighted V gather for the four rows ----
    const float* vbase = gv + (size_t)(b*H_ + h) * LM_ * DK_;
    #pragma unroll 1
    for (int rr = 0; rr < 4; rr++) {
        float v  = iordu(bval[rr]);
        float mx = v;
        #pragma unroll
        for (int off = 16; off; off >>= 1)
            mx = fmaxf(mx, __shfl_xor_sync(FULL, mx, off));
        float e = __expf(v - mx);
        float s = e;
        #pragma unroll
        for (int off = 16; off; off >>= 1)
            s += __shfl_xor_sync(FULL, s, off);
        float wgt = e / s;

        float a0 = 0.f, a1 = 0.f;
        #pragma unroll 4
        for (int it = 0; it < TOPK_; it++) {
            float wi = __shfl_sync(FULL, wgt, it);
            int   ki = __shfl_sync(FULL, bidx[rr], it);
            const float* vr = vbase + (size_t)ki * DK_;
            a0 = fmaf(wi, vr[lane],      a0);
            a1 = fmaf(wi, vr[lane + 32], a1);
        }
        float* orow = gx + ((size_t)b * LQ_ + (qt0 + 4*w + rr)) * DM_ + h*DK_;
        orow[lane]      = a0;
        orow[lane + 32] = a1;
    }
}

// ---------------------------------------------------------------------------
extern "C" void kernel_launch(void* const* d_in, const int* in_sizes, int n_in,
                              void* d_out, int out_size)
{
    const float* query = (const float*)d_in[0];
    const float* key   = (const float*)d_in[1];
    const float* value = (const float*)d_in[2];
    const float* Wq    = (const float*)d_in[3];
    const float* bq    = (const float*)d_in[4];
    const float* Wk    = (const float*)d_in[5];
    const float* bk    = (const float*)d_in[6];
    const float* Wv    = (const float*)d_in[7];
    const float* bv    = (const float*)d_in[8];
    const float* Wo    = (const float*)d_in[9];
    const float* bo    = (const float*)d_in[10];
    float* out = (float*)d_out;

    float *pq, *pk, *pv, *px;
    cudaGetSymbolAddress((void**)&pq, g_q);
    cudaGetSymbolAddress((void**)&pk, g_k);
    cudaGetSymbolAddress((void**)&pv, g_v);
    cudaGetSymbolAddress((void**)&px, g_x);

    cudaFuncSetAttribute(attn_topk_kernel,
                         cudaFuncAttributeMaxDynamicSharedMemorySize, SMEM_BYTES);

    // merged Q/K/V projections into head-major scratch (round-8 geometry)
    qkv_gemm_kernel<<<dim3(576, DM_/128), 256>>>(query, key, value,
                                                 Wq, bq, Wk, bk, Wv, bv,
                                                 pq, pk, pv);

    // fused scores + topk + softmax + gather
    attn_topk_kernel<<<dim3(LQ_/QT, H_, B_), 256, SMEM_BYTES>>>(pq, pk, pv, px);

    // output projection (plain row-major)
    out_gemm_kernel<<<dim3(B_*LQ_/128, DM_/128), 256>>>(px, Wo, bo, out);
}